// round 17
// baseline (speedup 1.0000x reference)
#include <cuda_runtime.h>
#include <cuda_fp16.h>
#include <cstdint>

#define BATCH 2
#define CH    64
#define NTOK  4608
#define BM    64
#define BN    64
#define NT    72               // total KV tiles
#define NS    4                // KV streams
#define NTH   18               // tiles per stream
#define SCALE 0.125f
#define LOG2E 1.4426950408889634f
#define PH    72               // padded tile row length in halves (144 B)
#define ONES2 0x3C003C00u      // half2(1.0, 1.0)

// Scratch (fp16): Q,K token-major [B][N][C]; V channel-major [B][C][N]
__device__ __half g_Q[BATCH * NTOK * CH];
__device__ __half g_K[BATCH * NTOK * CH];
__device__ __half g_V[BATCH * CH * NTOK];

// ---------------------------------------------------------------------------
__device__ __forceinline__ void mma_f16(float* c, const uint32_t* a,
                                        uint32_t b0, uint32_t b1) {
    asm volatile(
        "mma.sync.aligned.m16n8k16.row.col.f32.f16.f16.f32 "
        "{%0,%1,%2,%3}, {%4,%5,%6,%7}, {%8,%9}, {%0,%1,%2,%3};"
        : "+f"(c[0]), "+f"(c[1]), "+f"(c[2]), "+f"(c[3])
        : "r"(a[0]), "r"(a[1]), "r"(a[2]), "r"(a[3]), "r"(b0), "r"(b1));
}
__device__ __forceinline__ void ldm4(uint32_t& r0, uint32_t& r1,
                                     uint32_t& r2, uint32_t& r3, uint32_t addr) {
    asm volatile("ldmatrix.sync.aligned.m8n8.x4.shared.b16 {%0,%1,%2,%3}, [%4];"
                 : "=r"(r0), "=r"(r1), "=r"(r2), "=r"(r3) : "r"(addr));
}
__device__ __forceinline__ void cp16(uint32_t dst, const void* src) {
    asm volatile("cp.async.ca.shared.global [%0], [%1], 16;"
                 :: "r"(dst), "l"(src));
}
// pack {lo=slo, hi=shi} as f16x2
__device__ __forceinline__ uint32_t cvt2h(float shi, float slo) {
    uint32_t d;
    asm("cvt.rn.f16x2.f32 %0, %1, %2;" : "=r"(d) : "f"(shi), "f"(slo));
    return d;
}
// two exp2 in one MUFU op
__device__ __forceinline__ uint32_t ex2h2(uint32_t a) {
    uint32_t d;
    asm("ex2.approx.f16x2 %0, %1;" : "=r"(d) : "r"(a));
    return d;
}

// ---------------------------------------------------------------------------
// Tensor-core projection (unchanged).
// ---------------------------------------------------------------------------
__global__ __launch_bounds__(256) void proj_kernel(
    const float* __restrict__ x, const float* __restrict__ h,
    const float* __restrict__ Wq, const float* __restrict__ bq,
    const float* __restrict__ Wk, const float* __restrict__ bk,
    const float* __restrict__ Wv, const float* __restrict__ bv)
{
    __shared__ __half Wh[64 * PH];
    __shared__ __half Xh[128 * PH];
    __shared__ float  bsh[64];

    const int z = blockIdx.z;
    const float* inp  = (z == 0) ? x  : h;
    const float* W    = (z == 0) ? Wq : (z == 1) ? Wk : Wv;
    const float* bias = (z == 0) ? bq : (z == 1) ? bk : bv;

    const int tid = threadIdx.x;
    const int b   = blockIdx.y;
    const int n0  = blockIdx.x * 128;

    #pragma unroll
    for (int i = tid; i < 64 * 64; i += 256) {
        const int o = i >> 6, c = i & 63;
        Wh[o * PH + c] = __float2half_rn(W[i]);
    }
    if (tid < 64) bsh[tid] = bias[tid];

    const float* ib = inp + (size_t)b * CH * NTOK + n0;
    #pragma unroll
    for (int i = tid; i < 64 * 128; i += 256) {
        const int c = i >> 7, n = i & 127;
        Xh[n * PH + c] = __float2half_rn(ib[(size_t)c * NTOK + n]);
    }
    __syncthreads();

    const int lane = tid & 31;
    const int w    = tid >> 5;
    const int gid  = lane >> 2;
    const int lc   = lane & 3;
    const int rlow  = w * 16 + gid;
    const int rhigh = rlow + 8;

    uint32_t qa[4][4];
    #pragma unroll
    for (int kt = 0; kt < 4; kt++) {
        qa[kt][0] = *(const uint32_t*)&Xh[rlow  * PH + kt * 16 + 2 * lc];
        qa[kt][1] = *(const uint32_t*)&Xh[rhigh * PH + kt * 16 + 2 * lc];
        qa[kt][2] = *(const uint32_t*)&Xh[rlow  * PH + kt * 16 + 2 * lc + 8];
        qa[kt][3] = *(const uint32_t*)&Xh[rhigh * PH + kt * 16 + 2 * lc + 8];
    }

    const int lmm = lane >> 3, lmr = lane & 7;
    const uint32_t lmoff =
        (uint32_t)((((lmm >> 1) * 8 + lmr) * 144) + (lmm & 1) * 16);
    const uint32_t wbase = (uint32_t)__cvta_generic_to_shared(Wh) + lmoff;

    float acc[8][4];
    #pragma unroll
    for (int nt = 0; nt < 8; nt++)
        #pragma unroll
        for (int i = 0; i < 4; i++) acc[nt][i] = 0.f;

    #pragma unroll
    for (int kt = 0; kt < 4; kt++) {
        #pragma unroll
        for (int ntp = 0; ntp < 4; ntp++) {
            uint32_t r0, r1, r2, r3;
            ldm4(r0, r1, r2, r3, wbase + ntp * 2304 + kt * 32);
            mma_f16(acc[2 * ntp],     qa[kt], r0, r1);
            mma_f16(acc[2 * ntp + 1], qa[kt], r2, r3);
        }
    }

    if (z == 2) {
        __syncthreads();
        __half* Vt2 = Xh;                      // [64 c][132 n-pad]
        #pragma unroll
        for (int nt = 0; nt < 8; nt++) {
            const int c0 = nt * 8 + 2 * lc;
            Vt2[(c0)     * 132 + rlow]  = __float2half_rn(acc[nt][0] + bsh[c0]);
            Vt2[(c0 + 1) * 132 + rlow]  = __float2half_rn(acc[nt][1] + bsh[c0 + 1]);
            Vt2[(c0)     * 132 + rhigh] = __float2half_rn(acc[nt][2] + bsh[c0]);
            Vt2[(c0 + 1) * 132 + rhigh] = __float2half_rn(acc[nt][3] + bsh[c0 + 1]);
        }
        __syncthreads();
        __half* vd = g_V + (size_t)b * CH * NTOK + n0;
        #pragma unroll
        for (int i = tid; i < 64 * 64; i += 256) {
            const int c = i >> 6, n2 = (i & 63) * 2;
            *(__half2*)&vd[(size_t)c * NTOK + n2] = *(__half2*)&Vt2[c * 132 + n2];
        }
    } else {
        const float qs = (z == 0) ? SCALE * LOG2E : 1.f;
        __half* base = (z == 0) ? g_Q : g_K;
        __half* dlo = base + ((size_t)(b * NTOK + n0 + rlow))  * CH;
        __half* dhi = base + ((size_t)(b * NTOK + n0 + rhigh)) * CH;
        #pragma unroll
        for (int nt = 0; nt < 8; nt++) {
            const int c0 = nt * 8 + 2 * lc;
            const float b0 = bsh[c0], b1 = bsh[c0 + 1];
            __half2 lo = __floats2half2_rn((acc[nt][0] + b0) * qs,
                                           (acc[nt][1] + b1) * qs);
            __half2 hi = __floats2half2_rn((acc[nt][2] + b0) * qs,
                                           (acc[nt][3] + b1) * qs);
            *(__half2*)&dlo[c0] = lo;
            *(__half2*)&dhi[c0] = hi;
        }
    }
}

// ---------------------------------------------------------------------------
// 4-way split-KV, m32 warp tiles, FUSED kj-chunk pipeline:
// per chunk: QK(16 kj) -> exp -> lacc -> PV — QK(chunk+1) is independent of
// exp/PV(chunk) so tensor work fills the MUFU/pack latency. 256 thr, 8 warps.
// smem: Qs @0 (9216); K [4 streams][2 slots] @9216; V @+8*9216. 156672 B.
// ---------------------------------------------------------------------------
#define QS_B 0
#define KS_B 9216
#define VS_B (KS_B + 8 * 9216)
#define SMEM_BYTES (VS_B + 8 * 9216)   // 156672

__global__ __launch_bounds__(256, 1) void attn_kernel(float* __restrict__ out)
{
    extern __shared__ char smc[];
    const uint32_t sb = (uint32_t)__cvta_generic_to_shared(smc);

    const int b    = blockIdx.y;
    const int m0   = blockIdx.x * BM;
    const int tid  = threadIdx.x;
    const int lane = tid & 31;
    const int w    = tid >> 5;
    const int rg   = w & 1;              // rows rg*32..+31
    const int ks   = w >> 1;             // stream 0..3
    const int gtid = tid & 63;           // thread-in-group (2 warps)
    const int gid  = lane >> 2;
    const int lc   = lane & 3;

    const int lmm = lane >> 3, lmr = lane & 7;
    const uint32_t lmoff =
        (uint32_t)((((lmm >> 1) * 8 + lmr) * 144) + (lmm & 1) * 16);

    auto stage_kv = [&](int slot, int tl) {
        const int tn = ks * NTH + tl;
        const uint32_t koff = sb + KS_B + (ks * 2 + slot) * 9216;
        const uint32_t voff = sb + VS_B + (ks * 2 + slot) * 9216;
        #pragma unroll
        for (int i = 0; i < 8; i++) {
            const int j = gtid + i * 64;      // 0..511
            const int r = j >> 3, c8 = j & 7;
            cp16(koff + r * 144 + c8 * 16,
                 g_K + ((size_t)(b * NTOK + tn * BN) + r) * CH + c8 * 8);
            cp16(voff + r * 144 + c8 * 16,
                 g_V + (size_t)b * CH * NTOK + (size_t)r * NTOK
                     + tn * BN + c8 * 8);
        }
    };

    // ---- prologue: Q + slot0(t0), slot1(t1) ----
    {
        #pragma unroll
        for (int i = 0; i < 2; i++) {
            const int j = tid + i * 256;
            const int r = j >> 3, c8 = j & 7;
            cp16(sb + QS_B + r * 144 + c8 * 16,
                 g_Q + ((size_t)(b * NTOK + m0) + r) * CH + c8 * 8);
        }
        stage_kv(0, 0);
        asm volatile("cp.async.commit_group;");
        stage_kv(1, 1);
        asm volatile("cp.async.commit_group;");
        asm volatile("cp.async.wait_group 1;" ::: "memory");  // Q + tile0
        __syncthreads();
    }

    // ---- persistent Q A-fragments, two m16 halves ----
    const __half* Qs = (const __half*)(smc + QS_B);
    uint32_t qa[2][4][4];
    #pragma unroll
    for (int sm = 0; sm < 2; sm++) {
        const int rl = rg * 32 + sm * 16 + gid;
        const int rh = rl + 8;
        #pragma unroll
        for (int kt = 0; kt < 4; kt++) {
            qa[sm][kt][0] = *(const uint32_t*)&Qs[rl * PH + kt * 16 + 2 * lc];
            qa[sm][kt][1] = *(const uint32_t*)&Qs[rh * PH + kt * 16 + 2 * lc];
            qa[sm][kt][2] = *(const uint32_t*)&Qs[rl * PH + kt * 16 + 2 * lc + 8];
            qa[sm][kt][3] = *(const uint32_t*)&Qs[rh * PH + kt * 16 + 2 * lc + 8];
        }
    }

    float acc[2][8][4];
    #pragma unroll
    for (int sm = 0; sm < 2; sm++)
        #pragma unroll
        for (int nt = 0; nt < 8; nt++)
            #pragma unroll
            for (int i = 0; i < 4; i++) acc[sm][nt][i] = 0.f;
    float lacc[2][4];                        // row sums via P x ones mma
    #pragma unroll
    for (int sm = 0; sm < 2; sm++)
        #pragma unroll
        for (int i = 0; i < 4; i++) lacc[sm][i] = 0.f;

    const int barid = ks + 1;

    for (int t = 0; t < NTH; t++) {
        const int slot = t & 1;
        const uint32_t kbase = sb + KS_B + (ks * 2 + slot) * 9216 + lmoff;
        const uint32_t vbase = sb + VS_B + (ks * 2 + slot) * 9216 + lmoff;

        // ---- fused per-kj-chunk pipeline (4 chunks of 16 kj) ----
        #pragma unroll
        for (int ntp = 0; ntp < 4; ntp++) {
            // QK for this chunk: 4 ldm4 (kt) x 4 mma each
            float s[2][2][4];
            #pragma unroll
            for (int sm = 0; sm < 2; sm++)
                #pragma unroll
                for (int nt = 0; nt < 2; nt++)
                    #pragma unroll
                    for (int i = 0; i < 4; i++) s[sm][nt][i] = 0.f;

            #pragma unroll
            for (int kt = 0; kt < 4; kt++) {
                uint32_t r0, r1, r2, r3;
                ldm4(r0, r1, r2, r3, kbase + ntp * 2304 + kt * 32);
                mma_f16(s[0][0], qa[0][kt], r0, r1);
                mma_f16(s[0][1], qa[0][kt], r2, r3);
                mma_f16(s[1][0], qa[1][kt], r0, r1);
                mma_f16(s[1][1], qa[1][kt], r2, r3);
            }

            // exp: 8 cvt + 8 ex2 (f16x2) -> pa chunk (dies after PV below)
            uint32_t pa[2][4];
            #pragma unroll
            for (int sm = 0; sm < 2; sm++) {
                pa[sm][0] = ex2h2(cvt2h(s[sm][0][1], s[sm][0][0]));
                pa[sm][1] = ex2h2(cvt2h(s[sm][0][3], s[sm][0][2]));
                pa[sm][2] = ex2h2(cvt2h(s[sm][1][1], s[sm][1][0]));
                pa[sm][3] = ex2h2(cvt2h(s[sm][1][3], s[sm][1][2]));
            }

            // row sums for this chunk
            mma_f16(lacc[0], pa[0], ONES2, ONES2);
            mma_f16(lacc[1], pa[1], ONES2, ONES2);

            // PV for this kj chunk: 4 ldm4 (channel pairs) x 4 mma each
            #pragma unroll
            for (int cp = 0; cp < 4; cp++) {
                uint32_t r0, r1, r2, r3;
                ldm4(r0, r1, r2, r3, vbase + cp * 2304 + ntp * 32);
                mma_f16(acc[0][2 * cp],     pa[0], r0, r1);
                mma_f16(acc[0][2 * cp + 1], pa[0], r2, r3);
                mma_f16(acc[1][2 * cp],     pa[1], r0, r1);
                mma_f16(acc[1][2 * cp + 1], pa[1], r2, r3);
            }
        }

        // ---- rotate buffers ----
        asm volatile("bar.sync %0, 64;" :: "r"(barid) : "memory");
        {
            int tl = t + 2; if (tl >= NTH) tl -= NTH;
            stage_kv(slot, tl);
            asm volatile("cp.async.commit_group;");
        }
        asm volatile("cp.async.wait_group 1;" ::: "memory");
        asm volatile("bar.sync %0, 64;" :: "r"(barid) : "memory");
    }

    // ---- l directly from lacc (mma already reduced across the quad) ----
    float lsum[2][2];
    #pragma unroll
    for (int sm = 0; sm < 2; sm++) {
        lsum[sm][0] = lacc[sm][0];   // rows gid
        lsum[sm][1] = lacc[sm][2];   // rows gid+8
    }

    // ---- 4-way merge: plain sums ----
    asm volatile("cp.async.wait_group 0;" ::: "memory");
    __syncthreads();
    float* mg = (float*)smc;                 // reuse staging smem (drained)
    const int lslot = rg * 32 + lane;        // 0..63
    if (ks != 0) {
        const int mb = ((ks - 1) * 64 + lslot) * 71;
        #pragma unroll
        for (int sm = 0; sm < 2; sm++)
            #pragma unroll
            for (int nt = 0; nt < 8; nt++)
                #pragma unroll
                for (int i = 0; i < 4; i++)
                    mg[mb + sm * 32 + nt * 4 + i] = acc[sm][nt][i];
        mg[mb + 64] = lsum[0][0]; mg[mb + 65] = lsum[0][1];
        mg[mb + 66] = lsum[1][0]; mg[mb + 67] = lsum[1][1];
    }
    __syncthreads();
    if (ks == 0) {
        const int mb1 = (lslot) * 71;
        const int mb2 = (64 + lslot) * 71;
        const int mb3 = (128 + lslot) * 71;
        float* ob = out + (size_t)b * CH * NTOK + m0;

        #pragma unroll
        for (int sm = 0; sm < 2; sm++) {
            #pragma unroll
            for (int half = 0; half < 2; half++) {
                const float L = lsum[sm][half]
                              + mg[mb1 + 64 + sm * 2 + half]
                              + mg[mb2 + 64 + sm * 2 + half]
                              + mg[mb3 + 64 + sm * 2 + half];
                const float inv = 1.f / L;
                const int row = rg * 32 + sm * 16 + gid + half * 8;
                const int i0 = half * 2, i1 = half * 2 + 1;

                #pragma unroll
                for (int nt = 0; nt < 8; nt++) {
                    const int c = nt * 8 + 2 * lc;
                    const float oA = (acc[sm][nt][i0]
                                      + mg[mb1 + sm * 32 + nt * 4 + i0]
                                      + mg[mb2 + sm * 32 + nt * 4 + i0]
                                      + mg[mb3 + sm * 32 + nt * 4 + i0]) * inv;
                    const float oB = (acc[sm][nt][i1]
                                      + mg[mb1 + sm * 32 + nt * 4 + i1]
                                      + mg[mb2 + sm * 32 + nt * 4 + i1]
                                      + mg[mb3 + sm * 32 + nt * 4 + i1]) * inv;
                    ob[(size_t)c * NTOK + row]       = oA;
                    ob[(size_t)(c + 1) * NTOK + row] = oB;
                }
            }
        }
    }
}

// ---------------------------------------------------------------------------
extern "C" void kernel_launch(void* const* d_in, const int* in_sizes, int n_in,
                              void* d_out, int out_size)
{
    const float* x  = (const float*)d_in[0];
    const float* h  = (const float*)d_in[1];
    const float* Wq = (const float*)d_in[2];
    const float* bq = (const float*)d_in[3];
    const float* Wk = (const float*)d_in[4];
    const float* bk = (const float*)d_in[5];
    const float* Wv = (const float*)d_in[6];
    const float* bv = (const float*)d_in[7];
    float* out = (float*)d_out;

    cudaFuncSetAttribute(attn_kernel,
                         cudaFuncAttributeMaxDynamicSharedMemorySize, SMEM_BYTES);

    proj_kernel<<<dim3(NTOK / 128, BATCH, 3), 256>>>(x, h, Wq, bq, Wk, bk, Wv, bv);
    attn_kernel<<<dim3(NTOK / BM, BATCH), 256, SMEM_BYTES>>>(out);
}